// round 1
// baseline (speedup 1.0000x reference)
#include <cuda_runtime.h>
#include <math.h>

#define L_TOTAL 131072
#define NBATCH  8
#define CHUNK   256
#define WARM    1792
#define SKEW    6
#define NCHUNK  (L_TOTAL / CHUNK)          // 512
#define NTHREADS (NCHUNK * NBATCH)         // 4096
#define BLOCK   32

__device__ __forceinline__ float ex2a(float x) {
    float y; asm("ex2.approx.ftz.f32 %0, %1;" : "=f"(y) : "f"(x)); return y;
}
__device__ __forceinline__ float rcpa(float x) {
    float y; asm("rcp.approx.ftz.f32 %0, %1;" : "=f"(y) : "f"(x)); return y;
}

struct BQ {
    float b0, b1, b2, a1, a2, s1, s2;
    __device__ __forceinline__ void init(float B0, float B1, float B2, float A1, float A2) {
        b0 = B0; b1 = B1; b2 = B2; a1 = A1; a2 = A2; s1 = 0.f; s2 = 0.f;
    }
    __device__ __forceinline__ float step(float x) {
        float y = fmaf(b0, x, s1);
        float t = fmaf(b1, x, s2);
        s1 = fmaf(-a1, y, t);
        s2 = fmaf(-a2, y, b2 * x);
        return y;
    }
};

// _stable(): b = raw[0..2]; a1 = 2*tanh(raw3); a2 = ((2-|a1|)*tanh(raw4)+|a1|)/2
__device__ __forceinline__ void mk_stable(const float* p, BQ& q) {
    float a1 = 2.f * tanhf(p[3]);
    float aa = fabsf(a1);
    float a2 = 0.5f * fmaf(2.f - aa, tanhf(p[4]), aa);
    q.init(p[0], p[1], p[2], a1, a2);
}

__global__ void __launch_bounds__(BLOCK, 1) amp_kernel(
    const float* __restrict__ X,     const float* __restrict__ knobs,
    const float* __restrict__ ecr,   const float* __restrict__ prep,
    const float* __restrict__ postp, const float* __restrict__ gwi,
    const float* __restrict__ gwh,   const float* __restrict__ gbi,
    const float* __restrict__ gbh,   const float* __restrict__ gow,
    const float* __restrict__ gob,   const float* __restrict__ sw1,
    const float* __restrict__ sb1,   const float* __restrict__ sw2,
    const float* __restrict__ sb2,   const float* __restrict__ fw1,
    const float* __restrict__ fb1,   const float* __restrict__ fw2,
    const float* __restrict__ fb2,   const float* __restrict__ famt,
    float* __restrict__ OUT)
{
    const int tid = blockIdx.x * BLOCK + threadIdx.x;
    if (tid >= NTHREADS) return;
    const int b = tid & (NBATCH - 1);
    const int c = tid >> 3;

    // ---------- per-thread setup (accurate transcendentals, runs once) ----------
    const float cenv  = 1.f / (1.f + expf(-ecr[0]));
    const float ccenv = 1.f - cenv;

    // sag depth (per batch)
    const float k0 = knobs[b * 3 + 0];
    float acc = sb2[0];
#pragma unroll
    for (int j = 0; j < 8; j++) acc += sw2[j] * tanhf(fmaf(k0, sw1[j], sb1[j]));
    const float depth = 1.f / (1.f + expf(-acc));

    BQ bq1, bq2, bq3, bq4, bqf;
    mk_stable(prep + 0, bq1);  mk_stable(prep + 5, bq2);
    mk_stable(postp + 0, bq3); mk_stable(postp + 5, bq4);

    // feedback biquad coefs (per batch)
    {
        const float k1 = knobs[b * 3 + 1], k2 = knobs[b * 3 + 2];
        float h16[16];
#pragma unroll
        for (int j = 0; j < 16; j++)
            h16[j] = tanhf(fmaf(k1, fw1[j * 2 + 0], fmaf(k2, fw1[j * 2 + 1], fb1[j])));
        float raw[5];
#pragma unroll
        for (int i = 0; i < 5; i++) {
            float a = fb2[i];
#pragma unroll
            for (int j = 0; j < 16; j++) a = fmaf(fw2[i * 16 + j], h16[j], a);
            raw[i] = a;
        }
        mk_stable(raw, bqf);
    }
    const float fbmix = 1.f / (1.f + expf(-famt[0]));

    // GRU constants (fold -log2(e) scaling into the sigmoid args)
    const float L2E = 1.4426950408889634f;
    const float wi2 = gwi[2], wh2 = gwh[2], bi2 = gbi[2], bh2 = gbh[2];
    const float ow = gow[0], ob = gob[0];
    const float rwx = -L2E * gwi[0], rwh = -L2E * gwh[0], rc = -L2E * (gbi[0] + gbh[0]);
    const float zwx = -L2E * gwi[1], zwh = -L2E * gwh[1], zc = -L2E * (gbi[1] + gbh[1]);
    const float NL2E = -2.f * L2E;

    // ---------- chunk geometry ----------
    const int out_start = c * CHUNK;
    const int out_end   = out_start + CHUNK;
    int base = out_start - WARM; if (base < 0) base = 0;
    const int iters  = (out_end - base) + SKEW;
    const int wstart = (out_start - base) + SKEW;

    const float* __restrict__ xr = X + (size_t)b * L_TOTAL;
    float* __restrict__ orow     = OUT + (size_t)b * L_TOTAL;

    float env = 0.f, h = 0.f;
    float d0 = 0.f, d1 = 0.f, d2 = 0.f, d3 = 0.f, d4 = 0.f, d5 = 0.f;

    // ---------- prologue: first SKEW iterations with GRU start-guard ----------
#pragma unroll
    for (int i = 0; i < SKEW; i++) {
        float y1 = bq1.step(d0);
        float y2 = bq2.step(d1);
        float y3 = 0.f;
        if (i >= 3) {
            float gh2v = fmaf(h, wh2, bh2);
            float gi2v = fmaf(d2, wi2, bi2);
            float er = ex2a(fmaf(h, rwh, fmaf(d2, rwx, rc)));
            float ez = ex2a(fmaf(h, zwh, fmaf(d2, zwx, zc)));
            float r = rcpa(1.f + er);
            float z = rcpa(1.f + ez);
            float narg = fmaf(r, gh2v, gi2v);
            float en = ex2a(narg * NL2E);
            float n = fmaf(2.f, rcpa(1.f + en), -1.f);
            h = fmaf(z, h - n, n);
            y3 = fmaf(h, ow, ob);
        }
        float y4 = bq3.step(d3);
        float y5 = bq4.step(d4);
        (void)bqf.step(d5);              // fb filter warms with zeros (no output yet)
        float xv = xr[base + i];
        env = fmaf(cenv, env, ccenv * fabsf(xv));
        float y0 = xv * fmaf(-depth, env, 1.f);
        d5 = y5; d4 = y4; d3 = y3; d2 = y2; d1 = y1; d0 = y0;
    }

    // ---------- main skewed-pipeline loop ----------
#pragma unroll 2
    for (int i = SKEW; i < iters; i++) {
        int s = base + i;
        float xv = xr[s < L_TOTAL ? s : (L_TOTAL - 1)];

        float y1 = bq1.step(d0);
        float y2 = bq2.step(d1);

        // GRU (stage 3): critical chain = FFMA -> EX2 -> FADD -> RCP -> FFMA -> FMUL
        //                -> EX2 -> FADD -> RCP -> FFMA -> FADD -> FFMA  (~96 cyc)
        float gh2v = fmaf(h, wh2, bh2);
        float gi2v = fmaf(d2, wi2, bi2);
        float er = ex2a(fmaf(h, rwh, fmaf(d2, rwx, rc)));
        float ez = ex2a(fmaf(h, zwh, fmaf(d2, zwx, zc)));
        float r = rcpa(1.f + er);
        float z = rcpa(1.f + ez);
        float narg = fmaf(r, gh2v, gi2v);
        float en = ex2a(narg * NL2E);
        float n = fmaf(2.f, rcpa(1.f + en), -1.f);
        h = fmaf(z, h - n, n);
        float y3 = fmaf(h, ow, ob);

        float y4 = bq3.step(d3);
        float y5 = bq4.step(d4);
        float yfb = bqf.step(d5);
        float ov = fmaf(-fbmix, yfb, d5);   // out(t) = y(t) - mix * fb(t), t = s - SKEW

        if (i >= wstart) orow[s - SKEW] = ov;

        env = fmaf(cenv, env, ccenv * fabsf(xv));
        float y0 = xv * fmaf(-depth, env, 1.f);

        d5 = y5; d4 = y4; d3 = y3; d2 = y2; d1 = y1; d0 = y0;
    }
}

extern "C" void kernel_launch(void* const* d_in, const int* in_sizes, int n_in,
                              void* d_out, int out_size)
{
    const float* X     = (const float*)d_in[0];
    const float* knobs = (const float*)d_in[1];
    const float* ecr   = (const float*)d_in[2];
    const float* prep  = (const float*)d_in[3];
    const float* postp = (const float*)d_in[4];
    const float* gwi   = (const float*)d_in[5];
    const float* gwh   = (const float*)d_in[6];
    const float* gbi   = (const float*)d_in[7];
    const float* gbh   = (const float*)d_in[8];
    const float* gow   = (const float*)d_in[9];
    const float* gob   = (const float*)d_in[10];
    const float* sw1   = (const float*)d_in[11];
    const float* sb1   = (const float*)d_in[12];
    const float* sw2   = (const float*)d_in[13];
    const float* sb2   = (const float*)d_in[14];
    const float* fw1   = (const float*)d_in[15];
    const float* fb1   = (const float*)d_in[16];
    const float* fw2   = (const float*)d_in[17];
    const float* fb2   = (const float*)d_in[18];
    const float* famt  = (const float*)d_in[19];
    float* OUT = (float*)d_out;

    dim3 grid(NTHREADS / BLOCK);   // 128 blocks of 32 -> ~1 warp per SM
    amp_kernel<<<grid, BLOCK>>>(X, knobs, ecr, prep, postp, gwi, gwh, gbi, gbh,
                                gow, gob, sw1, sb1, sw2, sb2, fw1, fb1, fw2, fb2,
                                famt, OUT);
}

// round 3
// speedup vs baseline: 3.1652x; 3.1652x over previous
#include <cuda_runtime.h>
#include <math.h>

#define L_TOTAL 131072
#define NBATCH  8
#define CHUNK   64
#define WARM    512
#define SKEW    6
#define NCHUNK  (L_TOTAL / CHUNK)          // 2048
#define NTHREADS (NCHUNK * NBATCH)         // 16384
#define BLOCK   128                        // 4 warps -> one per SMSP

__device__ __forceinline__ float ex2a(float x) {
    float y; asm("ex2.approx.ftz.f32 %0, %1;" : "=f"(y) : "f"(x)); return y;
}
__device__ __forceinline__ float rcpa(float x) {
    float y; asm("rcp.approx.ftz.f32 %0, %1;" : "=f"(y) : "f"(x)); return y;
}

struct BQ {
    float b0, b1, b2, a1, a2, s1, s2;
    __device__ __forceinline__ void init(float B0, float B1, float B2, float A1, float A2) {
        b0 = B0; b1 = B1; b2 = B2; a1 = A1; a2 = A2; s1 = 0.f; s2 = 0.f;
    }
    __device__ __forceinline__ float step(float x) {
        float y = fmaf(b0, x, s1);
        float t = fmaf(b1, x, s2);
        s1 = fmaf(-a1, y, t);
        s2 = fmaf(-a2, y, b2 * x);
        return y;
    }
};

// _stable(): b = raw[0..2]; a1 = 2*tanh(raw3); a2 = ((2-|a1|)*tanh(raw4)+|a1|)/2
__device__ __forceinline__ void mk_stable(const float* p, BQ& q) {
    float a1 = 2.f * tanhf(p[3]);
    float aa = fabsf(a1);
    float a2 = 0.5f * fmaf(2.f - aa, tanhf(p[4]), aa);
    q.init(p[0], p[1], p[2], a1, a2);
}

__global__ void __launch_bounds__(BLOCK, 1) amp_kernel(
    const float* __restrict__ X,     const float* __restrict__ knobs,
    const float* __restrict__ ecr,   const float* __restrict__ prep,
    const float* __restrict__ postp, const float* __restrict__ gwi,
    const float* __restrict__ gwh,   const float* __restrict__ gbi,
    const float* __restrict__ gbh,   const float* __restrict__ gow,
    const float* __restrict__ gob,   const float* __restrict__ sw1,
    const float* __restrict__ sb1,   const float* __restrict__ sw2,
    const float* __restrict__ sb2,   const float* __restrict__ fw1,
    const float* __restrict__ fb1,   const float* __restrict__ fw2,
    const float* __restrict__ fb2,   const float* __restrict__ famt,
    float* __restrict__ OUT)
{
    const int tid = blockIdx.x * BLOCK + threadIdx.x;
    if (tid >= NTHREADS) return;
    const int b = tid & (NBATCH - 1);
    const int c = tid >> 3;

    // ---------- per-thread setup (accurate transcendentals, runs once) ----------
    const float cenv  = 1.f / (1.f + expf(-ecr[0]));
    const float ccenv = 1.f - cenv;

    // sag depth (per batch)
    const float k0 = knobs[b * 3 + 0];
    float acc = sb2[0];
#pragma unroll
    for (int j = 0; j < 8; j++) acc += sw2[j] * tanhf(fmaf(k0, sw1[j], sb1[j]));
    const float depth = 1.f / (1.f + expf(-acc));

    BQ bq1, bq2, bq3, bq4, bqf;
    mk_stable(prep + 0, bq1);  mk_stable(prep + 5, bq2);
    mk_stable(postp + 0, bq3); mk_stable(postp + 5, bq4);

    // feedback biquad coefs (per batch)
    {
        const float k1 = knobs[b * 3 + 1], k2 = knobs[b * 3 + 2];
        float h16[16];
#pragma unroll
        for (int j = 0; j < 16; j++)
            h16[j] = tanhf(fmaf(k1, fw1[j * 2 + 0], fmaf(k2, fw1[j * 2 + 1], fb1[j])));
        float raw[5];
#pragma unroll
        for (int i = 0; i < 5; i++) {
            float a = fb2[i];
#pragma unroll
            for (int j = 0; j < 16; j++) a = fmaf(fw2[i * 16 + j], h16[j], a);
            raw[i] = a;
        }
        mk_stable(raw, bqf);
    }
    const float fbmix = 1.f / (1.f + expf(-famt[0]));

    // GRU constants (fold -log2(e) scaling into the sigmoid args)
    const float L2E = 1.4426950408889634f;
    const float wi2 = gwi[2], wh2 = gwh[2], bi2 = gbi[2], bh2 = gbh[2];
    const float ow = gow[0], ob = gob[0];
    const float rwx = -L2E * gwi[0], rwh = -L2E * gwh[0], rc = -L2E * (gbi[0] + gbh[0]);
    const float zwx = -L2E * gwi[1], zwh = -L2E * gwh[1], zc = -L2E * (gbi[1] + gbh[1]);
    const float NL2E = -2.f * L2E;

    // ---------- chunk geometry ----------
    const int out_start = c * CHUNK;
    const int out_end   = out_start + CHUNK;
    int base = out_start - WARM; if (base < 0) base = 0;
    const int iters  = (out_end - base) + SKEW;
    const int wstart = (out_start - base) + SKEW;

    const float* __restrict__ xr = X + (size_t)b * L_TOTAL;
    float* __restrict__ orow     = OUT + (size_t)b * L_TOTAL;

    float env = 0.f, h = 0.f;
    float d0 = 0.f, d1 = 0.f, d2 = 0.f, d3 = 0.f, d4 = 0.f, d5 = 0.f;

    // ---------- prologue: first SKEW iterations with GRU start-guard ----------
#pragma unroll
    for (int i = 0; i < SKEW; i++) {
        float y1 = bq1.step(d0);
        float y2 = bq2.step(d1);
        float y3 = 0.f;
        if (i >= 3) {
            float gh2v = fmaf(h, wh2, bh2);
            float gi2v = fmaf(d2, wi2, bi2);
            float er = ex2a(fmaf(h, rwh, fmaf(d2, rwx, rc)));
            float ez = ex2a(fmaf(h, zwh, fmaf(d2, zwx, zc)));
            float r = rcpa(1.f + er);
            float z = rcpa(1.f + ez);
            float narg = fmaf(r, gh2v, gi2v);
            float en = ex2a(narg * NL2E);
            float n = fmaf(2.f, rcpa(1.f + en), -1.f);
            h = fmaf(z, h - n, n);
            y3 = fmaf(h, ow, ob);
        }
        float y4 = bq3.step(d3);
        float y5 = bq4.step(d4);
        (void)bqf.step(d5);              // fb filter warms with zeros (no output yet)
        float xv = xr[base + i];
        env = fmaf(cenv, env, ccenv * fabsf(xv));
        float y0 = xv * fmaf(-depth, env, 1.f);
        d5 = y5; d4 = y4; d3 = y3; d2 = y2; d1 = y1; d0 = y0;
    }

    // ---------- main skewed-pipeline loop ----------
#pragma unroll 2
    for (int i = SKEW; i < iters; i++) {
        int s = base + i;
        float xv = xr[s < L_TOTAL ? s : (L_TOTAL - 1)];

        float y1 = bq1.step(d0);
        float y2 = bq2.step(d1);

        // GRU (stage 3): critical chain = FFMA -> EX2 -> FADD -> RCP -> FFMA -> FMUL
        //                -> EX2 -> FADD -> RCP -> FFMA -> FADD -> FFMA  (~100 cyc)
        float gh2v = fmaf(h, wh2, bh2);
        float gi2v = fmaf(d2, wi2, bi2);
        float er = ex2a(fmaf(h, rwh, fmaf(d2, rwx, rc)));
        float ez = ex2a(fmaf(h, zwh, fmaf(d2, zwx, zc)));
        float r = rcpa(1.f + er);
        float z = rcpa(1.f + ez);
        float narg = fmaf(r, gh2v, gi2v);
        float en = ex2a(narg * NL2E);
        float n = fmaf(2.f, rcpa(1.f + en), -1.f);
        h = fmaf(z, h - n, n);
        float y3 = fmaf(h, ow, ob);

        float y4 = bq3.step(d3);
        float y5 = bq4.step(d4);
        float yfb = bqf.step(d5);
        float ov = fmaf(-fbmix, yfb, d5);   // out(t) = y(t) - mix * fb(t), t = s - SKEW

        if (i >= wstart) orow[s - SKEW] = ov;

        env = fmaf(cenv, env, ccenv * fabsf(xv));
        float y0 = xv * fmaf(-depth, env, 1.f);

        d5 = y5; d4 = y4; d3 = y3; d2 = y2; d1 = y1; d0 = y0;
    }
}

extern "C" void kernel_launch(void* const* d_in, const int* in_sizes, int n_in,
                              void* d_out, int out_size)
{
    const float* X     = (const float*)d_in[0];
    const float* knobs = (const float*)d_in[1];
    const float* ecr   = (const float*)d_in[2];
    const float* prep  = (const float*)d_in[3];
    const float* postp = (const float*)d_in[4];
    const float* gwi   = (const float*)d_in[5];
    const float* gwh   = (const float*)d_in[6];
    const float* gbi   = (const float*)d_in[7];
    const float* gbh   = (const float*)d_in[8];
    const float* gow   = (const float*)d_in[9];
    const float* gob   = (const float*)d_in[10];
    const float* sw1   = (const float*)d_in[11];
    const float* sb1   = (const float*)d_in[12];
    const float* sw2   = (const float*)d_in[13];
    const float* sb2   = (const float*)d_in[14];
    const float* fw1   = (const float*)d_in[15];
    const float* fb1   = (const float*)d_in[16];
    const float* fw2   = (const float*)d_in[17];
    const float* fb2   = (const float*)d_in[18];
    const float* famt  = (const float*)d_in[19];
    float* OUT = (float*)d_out;

    dim3 grid(NTHREADS / BLOCK);   // 128 blocks x 128 threads: 4 warps/SM, 1 per SMSP
    amp_kernel<<<grid, BLOCK>>>(X, knobs, ecr, prep, postp, gwi, gwh, gbi, gbh,
                                gow, gob, sw1, sb1, sw2, sb2, fw1, fb1, fw2, fb2,
                                famt, OUT);
}

// round 4
// speedup vs baseline: 4.6797x; 1.4785x over previous
#include <cuda_runtime.h>
#include <math.h>

#define L_TOTAL 131072
#define NBATCH  8
#define CHUNK   32
#define FWARM   160            // filter/GRU warm-up (poles decay fast)
#define ENVW    384            // exact envelope pre-scan length
#define SKEW    8
#define NCHUNK  (L_TOTAL / CHUNK)          // 4096
#define NTHREADS (NCHUNK * NBATCH)         // 32768
#define BLOCK   256                        // 8 warps -> 2 per SMSP

__device__ __forceinline__ float ex2a(float x) {
    float y; asm("ex2.approx.ftz.f32 %0, %1;" : "=f"(y) : "f"(x)); return y;
}
__device__ __forceinline__ float rcpa(float x) {
    float y; asm("rcp.approx.ftz.f32 %0, %1;" : "=f"(y) : "f"(x)); return y;
}

struct BQ {
    float b0, b1, b2, a1, a2, s1, s2;
    __device__ __forceinline__ void init(float B0, float B1, float B2, float A1, float A2) {
        b0 = B0; b1 = B1; b2 = B2; a1 = A1; a2 = A2; s1 = 0.f; s2 = 0.f;
    }
    __device__ __forceinline__ float step(float x) {
        float y = fmaf(b0, x, s1);
        float t = fmaf(b1, x, s2);
        s1 = fmaf(-a1, y, t);
        s2 = fmaf(-a2, y, b2 * x);
        return y;
    }
};

// _stable(): b = raw[0..2]; a1 = 2*tanh(raw3); a2 = ((2-|a1|)*tanh(raw4)+|a1|)/2
__device__ __forceinline__ void mk_stable(const float* p, BQ& q) {
    float a1 = 2.f * tanhf(p[3]);
    float aa = fabsf(a1);
    float a2 = 0.5f * fmaf(2.f - aa, tanhf(p[4]), aa);
    q.init(p[0], p[1], p[2], a1, a2);
}

__global__ void __launch_bounds__(BLOCK, 1) amp_kernel(
    const float* __restrict__ X,     const float* __restrict__ knobs,
    const float* __restrict__ ecr,   const float* __restrict__ prep,
    const float* __restrict__ postp, const float* __restrict__ gwi,
    const float* __restrict__ gwh,   const float* __restrict__ gbi,
    const float* __restrict__ gbh,   const float* __restrict__ gow,
    const float* __restrict__ gob,   const float* __restrict__ sw1,
    const float* __restrict__ sb1,   const float* __restrict__ sw2,
    const float* __restrict__ sb2,   const float* __restrict__ fw1,
    const float* __restrict__ fb1,   const float* __restrict__ fw2,
    const float* __restrict__ fb2,   const float* __restrict__ famt,
    float* __restrict__ OUT)
{
    const int tid = blockIdx.x * BLOCK + threadIdx.x;
    if (tid >= NTHREADS) return;
    const int b = tid & (NBATCH - 1);
    const int c = tid >> 3;

    // ---------- per-thread setup (accurate transcendentals, runs once) ----------
    const float cenv  = 1.f / (1.f + expf(-ecr[0]));
    const float ccenv = 1.f - cenv;

    // sag depth (per batch)
    const float k0 = knobs[b * 3 + 0];
    float acc = sb2[0];
#pragma unroll
    for (int j = 0; j < 8; j++) acc += sw2[j] * tanhf(fmaf(k0, sw1[j], sb1[j]));
    const float depth = 1.f / (1.f + expf(-acc));

    BQ bq1, bq2, bq3, bq4, bqf;
    mk_stable(prep + 0, bq1);  mk_stable(prep + 5, bq2);
    mk_stable(postp + 0, bq3); mk_stable(postp + 5, bq4);

    // feedback biquad coefs (per batch)
    {
        const float k1 = knobs[b * 3 + 1], k2 = knobs[b * 3 + 2];
        float h16[16];
#pragma unroll
        for (int j = 0; j < 16; j++)
            h16[j] = tanhf(fmaf(k1, fw1[j * 2 + 0], fmaf(k2, fw1[j * 2 + 1], fb1[j])));
        float raw[5];
#pragma unroll
        for (int i = 0; i < 5; i++) {
            float a = fb2[i];
#pragma unroll
            for (int j = 0; j < 16; j++) a = fmaf(fw2[i * 16 + j], h16[j], a);
            raw[i] = a;
        }
        mk_stable(raw, bqf);
    }
    const float fbmix = 1.f / (1.f + expf(-famt[0]));

    // GRU constants (fold -log2(e) / -2*log2(e) into the ex2 args)
    const float L2E = 1.4426950408889634f;
    const float NL2E = -2.f * L2E;
    const float ow = gow[0], ob = gob[0];
    const float rwx = -L2E * gwi[0], rwh = -L2E * gwh[0], rc = -L2E * (gbi[0] + gbh[0]);
    const float zwx = -L2E * gwi[1], zwh = -L2E * gwh[1], zc = -L2E * (gbi[1] + gbh[1]);
    const float wi2n = NL2E * gwi[2], bi2n = NL2E * gbi[2];
    const float wh2n = NL2E * gwh[2], bh2n = NL2E * gbh[2];

    // ---------- chunk geometry ----------
    const int out_start = c * CHUNK;
    const int out_end   = out_start + CHUNK;
    int fbase = out_start - FWARM; if (fbase < 0) fbase = 0;
    int ebase = fbase - ENVW;      if (ebase < 0) ebase = 0;
    const int iters  = (out_end - fbase) + SKEW;          // SKEW + multiple of 4
    const int wstart = (out_start - fbase) + SKEW;        // multiple of 4

    const float* __restrict__ xr = X + (size_t)b * L_TOTAL;
    float* __restrict__ orow     = OUT + (size_t)b * L_TOTAL;

    // ---------- exact envelope pre-scan, 4 samples per chain FMA ----------
    float env = 0.f;
    {
        const float c2 = cenv * cenv, c4 = c2 * c2;
        const float g0 = ccenv * cenv * c2;   // weight of sample t   (oldest in group)
        const float g1 = ccenv * c2;
        const float g2 = ccenv * cenv;
        const float g3 = ccenv;               // newest in group
        for (int t = ebase; t < fbase; t += 4) {
            float4 v = *reinterpret_cast<const float4*>(xr + t);
            float a = g0 * fabsf(v.x);
            a = fmaf(g1, fabsf(v.y), a);
            a = fmaf(g2, fabsf(v.z), a);
            a = fmaf(g3, fabsf(v.w), a);
            env = fmaf(c4, env, a);
        }
    }

    float h = 0.f;
    float d0 = 0.f, d1 = 0.f, d2 = 0.f, d3 = 0.f;
    float d4 = 0.f, d5 = 0.f, d6 = 0.f, d7 = 0.f;

    // ---------- prologue: first SKEW iterations (scalar loads, GRU guard) ----------
#pragma unroll
    for (int i = 0; i < SKEW; i++) {
        float y1 = bq1.step(d0);
        float y2 = bq2.step(d1);
        float y3 = 0.f;
        if (i >= 3) {
            float er = ex2a(fmaf(h, rwh, fmaf(d2, rwx, rc)));
            float ez = ex2a(fmaf(h, zwh, fmaf(d2, zwx, zc)));
            float r = rcpa(1.f + er);
            float z = rcpa(1.f + ez);
            float gi2s = fmaf(d2, wi2n, bi2n);
            float gh2s = fmaf(h, wh2n, bh2n);
            float en = ex2a(fmaf(r, gh2s, gi2s));
            float n = fmaf(2.f, rcpa(1.f + en), -1.f);
            h = fmaf(z, h - n, n);
            y3 = fmaf(h, ow, ob);
        }
        float y4 = bq3.step(d3);
        float y5 = bq4.step(d4);
        (void)bqf.step(d7);              // state stays zero until d7 is live
        float xv = xr[fbase + i];
        env = fmaf(cenv, env, ccenv * fabsf(xv));
        float y0 = xv * fmaf(-depth, env, 1.f);
        d7 = d6; d6 = d5; d5 = y5; d4 = y4; d3 = y3; d2 = y2; d1 = y1; d0 = y0;
    }

    // ---------- main skewed-pipeline loop, 4-wide with vector I/O ----------
    for (int i = SKEW; i < iters; i += 4) {
        const int s = fbase + i;
        float xv4[4];
        if (s + 3 < L_TOTAL) {
            float4 v = *reinterpret_cast<const float4*>(xr + s);
            xv4[0] = v.x; xv4[1] = v.y; xv4[2] = v.z; xv4[3] = v.w;
        } else {
#pragma unroll
            for (int j = 0; j < 4; j++) {
                int ss = s + j; if (ss > L_TOTAL - 1) ss = L_TOTAL - 1;
                xv4[j] = xr[ss];
            }
        }

        float ov4[4];
#pragma unroll
        for (int j = 0; j < 4; j++) {
            float xv = xv4[j];

            float y1 = bq1.step(d0);
            float y2 = bq2.step(d1);

            // GRU: chain h -> FFMA -> EX2 -> FADD -> RCP -> FFMA -> EX2 -> FADD
            //      -> RCP -> FFMA -> FADD -> FFMA  (~96 cyc)
            float er = ex2a(fmaf(h, rwh, fmaf(d2, rwx, rc)));
            float ez = ex2a(fmaf(h, zwh, fmaf(d2, zwx, zc)));
            float r = rcpa(1.f + er);
            float z = rcpa(1.f + ez);
            float gi2s = fmaf(d2, wi2n, bi2n);
            float gh2s = fmaf(h, wh2n, bh2n);
            float en = ex2a(fmaf(r, gh2s, gi2s));
            float n = fmaf(2.f, rcpa(1.f + en), -1.f);
            h = fmaf(z, h - n, n);
            float y3 = fmaf(h, ow, ob);

            float y4 = bq3.step(d3);
            float y5 = bq4.step(d4);
            float yfb = bqf.step(d7);
            ov4[j] = fmaf(-fbmix, yfb, d7);   // out(t) = y(t) - mix*fb(t), t = s+j-SKEW

            env = fmaf(cenv, env, ccenv * fabsf(xv));
            float y0 = xv * fmaf(-depth, env, 1.f);

            d7 = d6; d6 = d5; d5 = y5; d4 = y4; d3 = y3; d2 = y2; d1 = y1; d0 = y0;
        }

        if (i >= wstart) {
            float4 o; o.x = ov4[0]; o.y = ov4[1]; o.z = ov4[2]; o.w = ov4[3];
            *reinterpret_cast<float4*>(orow + (s - SKEW)) = o;
        }
    }
}

extern "C" void kernel_launch(void* const* d_in, const int* in_sizes, int n_in,
                              void* d_out, int out_size)
{
    const float* X     = (const float*)d_in[0];
    const float* knobs = (const float*)d_in[1];
    const float* ecr   = (const float*)d_in[2];
    const float* prep  = (const float*)d_in[3];
    const float* postp = (const float*)d_in[4];
    const float* gwi   = (const float*)d_in[5];
    const float* gwh   = (const float*)d_in[6];
    const float* gbi   = (const float*)d_in[7];
    const float* gbh   = (const float*)d_in[8];
    const float* gow   = (const float*)d_in[9];
    const float* gob   = (const float*)d_in[10];
    const float* sw1   = (const float*)d_in[11];
    const float* sb1   = (const float*)d_in[12];
    const float* sw2   = (const float*)d_in[13];
    const float* sb2   = (const float*)d_in[14];
    const float* fw1   = (const float*)d_in[15];
    const float* fb1   = (const float*)d_in[16];
    const float* fw2   = (const float*)d_in[17];
    const float* fb2   = (const float*)d_in[18];
    const float* famt  = (const float*)d_in[19];
    float* OUT = (float*)d_out;

    dim3 grid(NTHREADS / BLOCK);   // 128 blocks x 256 threads: 8 warps/SM, 2 per SMSP
    amp_kernel<<<grid, BLOCK>>>(X, knobs, ecr, prep, postp, gwi, gwh, gbi, gbh,
                                gow, gob, sw1, sb1, sw2, sb2, fw1, fb1, fw2, fb2,
                                famt, OUT);
}